// round 6
// baseline (speedup 1.0000x reference)
#include <cuda_runtime.h>
#include <cuda_fp16.h>
#include <stdint.h>
#include <math.h>

// ---------------- problem constants ----------------
constexpr int BB   = 4;
constexpr int CC   = 512;
constexpr int TT   = 16;
constexpr int HWc  = 1024;
constexpr int NN   = BB * HWc;      // 4096
constexpr int MM   = NN * TT;       // 65536
constexpr int NH   = 8;
constexpr int CH   = 64;
constexpr int GRP  = 32;
constexpr int CPG  = CC / GRP;      // 16
constexpr int C3   = 3 * CC;        // 1536
constexpr float EPSF = 1e-6f;

// ---------------- scratch (static device globals) ----------------
__device__ float g_mean[BB * GRP * HWc];
__device__ float g_rstd[BB * GRP * HWc];
__device__ __half g_nh[(size_t)MM * CC];
__device__ __half g_nl[(size_t)MM * CC];
__device__ __half g_wqh[C3 * CC], g_wql[C3 * CC];
__device__ __half g_wph[CC * CC], g_wpl[CC * CC];
__device__ float g_qkv[(size_t)MM * C3];
__device__ __half g_ah[(size_t)MM * CC];
__device__ __half g_al[(size_t)MM * CC];
__device__ float g_pout[(size_t)MM * CC];

// ---------------- helpers ----------------
__device__ __forceinline__ uint32_t smem_u32(const void* p) {
    uint32_t a;
    asm("{ .reg .u64 t; cvta.to.shared.u64 t, %1; cvt.u32.u64 %0, t; }" : "=r"(a) : "l"(p));
    return a;
}
__device__ __forceinline__ void cpasync16(uint32_t dst, const void* src) {
    asm volatile("cp.async.cg.shared.global [%0], [%1], 16;" :: "r"(dst), "l"(src));
}
__device__ __forceinline__ void ldsm4(uint32_t* r, uint32_t a) {
    asm volatile("ldmatrix.sync.aligned.m8n8.x4.shared.b16 {%0,%1,%2,%3}, [%4];"
                 : "=r"(r[0]), "=r"(r[1]), "=r"(r[2]), "=r"(r[3]) : "r"(a));
}
__device__ __forceinline__ void mma16816(float* d, const uint32_t* a, uint32_t b0, uint32_t b1) {
    asm volatile(
        "mma.sync.aligned.m16n8k16.row.col.f32.f16.f16.f32 "
        "{%0,%1,%2,%3},{%4,%5,%6,%7},{%8,%9},{%0,%1,%2,%3};"
        : "+f"(d[0]), "+f"(d[1]), "+f"(d[2]), "+f"(d[3])
        : "r"(a[0]), "r"(a[1]), "r"(a[2]), "r"(a[3]), "r"(b0), "r"(b1));
}
__device__ __forceinline__ float dot4(float4 a, float4 b) {
    return a.x * b.x + a.y * b.y + a.z * b.z + a.w * b.w;
}

// ---------------- 0) split both weight matrices (one launch) ----------------
__global__ __launch_bounds__(256) void conv_both(const float* __restrict__ wq,
                                                 const float* __restrict__ wp) {
    int i4 = blockIdx.x * 256 + threadIdx.x;
    constexpr int NQ4 = C3 * CC / 4;
    constexpr int NP4 = CC * CC / 4;
    const float4* src;
    __half *h, *l;
    int idx;
    if (i4 < NQ4) { src = (const float4*)wq; h = g_wqh; l = g_wql; idx = i4; }
    else if (i4 < NQ4 + NP4) { src = (const float4*)wp; h = g_wph; l = g_wpl; idx = i4 - NQ4; }
    else return;
    float4 v = src[idx];
    float vv[4] = {v.x, v.y, v.z, v.w};
    __half hh[4], ll[4];
    #pragma unroll
    for (int k = 0; k < 4; k++) {
        hh[k] = __float2half(vv[k]);
        ll[k] = __float2half(vv[k] - __half2float(hh[k]));
    }
    uint2 uh, ul;
    uh.x = *(uint32_t*)&hh[0]; uh.y = *(uint32_t*)&hh[2];
    ul.x = *(uint32_t*)&ll[0]; ul.y = *(uint32_t*)&ll[2];
    *(uint2*)(h + idx * 4) = uh;
    *(uint2*)(l + idx * 4) = ul;
}

// ---------------- 1) group-norm statistics ----------------
__global__ __launch_bounds__(1024) void gn_stats(const float* __restrict__ x) {
    int bg = blockIdx.x;
    int b  = bg >> 5;
    int g  = bg & 31;
    int hw = threadIdx.x;
    float sum = 0.f, sq = 0.f;
    const float* base = x + ((size_t)b * CC + (size_t)g * CPG) * TT * HWc + hw;
    #pragma unroll 4
    for (int ct = 0; ct < CPG * TT; ct++) {
        float v = base[(size_t)ct * HWc];
        sum += v; sq += v * v;
    }
    float m   = sum * (1.0f / 256.0f);
    float var = sq  * (1.0f / 256.0f) - m * m;
    g_mean[(size_t)bg * HWc + hw] = m;
    g_rstd[(size_t)bg * HWc + hw] = rsqrtf(var + EPSF);
}

// ---------------- 2) normalize + transpose to fp16 hi/lo [M,512] ----------------
__global__ __launch_bounds__(256) void norm_tr(const float* __restrict__ x,
                                               const float* __restrict__ gamma,
                                               const float* __restrict__ beta) {
    __shared__ float tile[32][33];
    int bx  = blockIdx.x;
    int hwt = bx & 31;
    int ct  = (bx >> 5) & 15;
    int t   = (bx >> 9) & 15;
    int b   = bx >> 13;
    int tid = threadIdx.x;
    {
        int hw_l = tid & 31;
        int c_l0 = tid >> 5;
        int hw   = hwt * 32 + hw_l;
        #pragma unroll
        for (int p = 0; p < 4; p++) {
            int c_l = c_l0 + p * 8;
            int c   = ct * 32 + c_l;
            int g   = c >> 4;
            float v = x[(((size_t)b * CC + c) * TT + t) * HWc + hw];
            size_t si = ((size_t)(b * GRP + g)) * HWc + hw;
            v = (v - g_mean[si]) * g_rstd[si] * gamma[c] + beta[c];
            tile[c_l][hw_l] = v;
        }
    }
    __syncthreads();
    {
        int c2    = (tid & 15) * 2;
        int hw_l0 = tid >> 4;
        #pragma unroll
        for (int p = 0; p < 2; p++) {
            int hw_l = hw_l0 + p * 16;
            int hw   = hwt * 32 + hw_l;
            size_t m = ((size_t)(b * HWc + hw)) * TT + t;
            float v0 = tile[c2][hw_l];
            float v1 = tile[c2 + 1][hw_l];
            __half h0 = __float2half(v0), h1 = __float2half(v1);
            __half l0 = __float2half(v0 - __half2float(h0));
            __half l1 = __float2half(v1 - __half2float(h1));
            size_t idx = m * CC + ct * 32 + c2;
            *(__half2*)(g_nh + idx) = __halves2half2(h0, h1);
            *(__half2*)(g_nl + idx) = __halves2half2(l0, l1);
        }
    }
}

// ---------------- HMMA GEMM: 2-stage, single sync/iter, hoisted addressing ----------------
constexpr int PITCH   = 80;
constexpr int TILE_B  = 128 * PITCH;   // 10240
constexpr int STAGE_B = 4 * TILE_B;    // 40960
constexpr int GEMM_SMEM = 2 * STAGE_B; // 81920

__global__ __launch_bounds__(256, 2) void hmma_gemm(const __half* __restrict__ Ah,
                                                    const __half* __restrict__ Al,
                                                    const __half* __restrict__ Bh,
                                                    const __half* __restrict__ Bl,
                                                    const float* __restrict__ bias,
                                                    float* __restrict__ Cout, int ldc) {
    extern __shared__ char smem[];
    uint32_t sb = smem_u32(smem);
    int tid = threadIdx.x;
    int n0 = blockIdx.x * 128;
    int m0 = blockIdx.y * 128;

    // hoisted loader state: thread owns rows (r, r+64), 16B col c, in all 4 tiles
    int r = tid >> 2;
    int c = tid & 3;
    const int4* pAh = (const int4*)Ah + (size_t)(m0 + r) * 64 + c;
    const int4* pAl = (const int4*)Al + (size_t)(m0 + r) * 64 + c;
    const int4* pBh = (const int4*)Bh + (size_t)(n0 + r) * 64 + c;
    const int4* pBl = (const int4*)Bl + (size_t)(n0 + r) * 64 + c;
    uint32_t d0 = sb + r * PITCH + c * 16;
    constexpr int RSTEP = 64 * 64;      // +64 rows in int4 units
    constexpr int DSTEP = 64 * PITCH;   // +64 rows in smem bytes

    auto issue = [&](int kk, int stage) {
        uint32_t dst = d0 + stage * STAGE_B;
        int ko = kk * 4;
        cpasync16(dst,                       pAh + ko);
        cpasync16(dst + DSTEP,               pAh + ko + RSTEP);
        cpasync16(dst + TILE_B,              pAl + ko);
        cpasync16(dst + TILE_B + DSTEP,      pAl + ko + RSTEP);
        cpasync16(dst + 2 * TILE_B,          pBh + ko);
        cpasync16(dst + 2 * TILE_B + DSTEP,  pBh + ko + RSTEP);
        cpasync16(dst + 3 * TILE_B,          pBl + ko);
        cpasync16(dst + 3 * TILE_B + DSTEP,  pBl + ko + RSTEP);
        asm volatile("cp.async.commit_group;");
    };

    float acc[4][4][4];
    #pragma unroll
    for (int a = 0; a < 4; a++)
        #pragma unroll
        for (int b = 0; b < 4; b++)
            #pragma unroll
            for (int cc = 0; cc < 4; cc++) acc[a][b][cc] = 0.f;

    int wid = tid >> 5, lane = tid & 31;
    int mw  = (wid >> 2) * 64;
    int nwv = (wid & 3) * 32;
    int lrow = lane & 15;
    int lk   = (lane >> 4) * 16;
    uint32_t adab = (mw + lrow) * PITCH + lk;               // A base (rel stage)
    uint32_t bdab = 2 * TILE_B + (nwv + lrow) * PITCH + lk; // Bh base (rel stage)

    issue(0, 0);

    #pragma unroll 1
    for (int ks = 0; ks < 16; ks++) {
        asm volatile("cp.async.wait_group 0;");
        __syncthreads();
        if (ks + 1 < 16) issue(ks + 1, (ks + 1) & 1);

        uint32_t sa = sb + (ks & 1) * STAGE_B;
        #pragma unroll
        for (int j = 0; j < 2; j++) {
            uint32_t ah[4][4], al[4][4], bh[2][4], bl[2][4];
            #pragma unroll
            for (int mt = 0; mt < 4; mt++) {
                uint32_t ad = sa + adab + mt * (16 * PITCH) + j * 32;
                ldsm4(ah[mt], ad);
                ldsm4(al[mt], ad + TILE_B);
            }
            #pragma unroll
            for (int bt = 0; bt < 2; bt++) {
                uint32_t bd = sa + bdab + bt * (16 * PITCH) + j * 32;
                ldsm4(bh[bt], bd);
                ldsm4(bl[bt], bd + TILE_B);
            }
            #pragma unroll
            for (int mt = 0; mt < 4; mt++)
                #pragma unroll
                for (int nt = 0; nt < 4; nt++) {
                    int bt = nt >> 1, s = nt & 1;
                    mma16816(acc[mt][nt], ah[mt], bh[bt][s], bh[bt][2 + s]);
                    mma16816(acc[mt][nt], ah[mt], bl[bt][s], bl[bt][2 + s]);
                    mma16816(acc[mt][nt], al[mt], bh[bt][s], bh[bt][2 + s]);
                }
        }
    }

    int row_in = lane >> 2;
    int colq   = (lane & 3) * 2;
    #pragma unroll
    for (int mt = 0; mt < 4; mt++) {
        int gr = m0 + mw + mt * 16 + row_in;
        #pragma unroll
        for (int nt = 0; nt < 4; nt++) {
            int gc = n0 + nwv + nt * 8 + colq;
            float b0 = bias[gc], b1 = bias[gc + 1];
            float2 v0 = make_float2(acc[mt][nt][0] + b0, acc[mt][nt][1] + b1);
            float2 v1 = make_float2(acc[mt][nt][2] + b0, acc[mt][nt][3] + b1);
            *(float2*)(Cout + (size_t)gr * ldc + gc)       = v0;
            *(float2*)(Cout + (size_t)(gr + 8) * ldc + gc) = v1;
        }
    }
}

// ---------------- 4) attention: one block per n, all 8 heads ----------------
constexpr int QP = 516;
constexpr int RP = 68;
constexpr int OFF_Q  = 0;
constexpr int OFF_K  = 16 * QP;
constexpr int OFF_V  = 32 * QP;
constexpr int OFF_RK = 48 * QP;
constexpr int OFF_RV = OFF_RK + 31 * RP;
constexpr int OFF_WS = OFF_RV + 31 * RP;
constexpr int ATTN_SMEM = (OFF_WS + 8 * 16 * 17) * 4;

__global__ __launch_bounds__(256, 1) void attn(const float* __restrict__ rp_k,
                                               const float* __restrict__ rp_v) {
    extern __shared__ float sm[];
    float* q  = sm + OFF_Q;
    float* k  = sm + OFF_K;
    float* v  = sm + OFF_V;
    float* rk = sm + OFF_RK;
    float* rv = sm + OFF_RV;
    float* ws = sm + OFF_WS;

    int n   = blockIdx.x;
    int tid = threadIdx.x;
    const float scale = 0.35355339059327373f;

    const float4* gq = reinterpret_cast<const float4*>(g_qkv);
    #pragma unroll
    for (int it = 0; it < 24; it++) {
        int idx = it * 256 + tid;
        int t   = idx / 384;
        int rem = idx - t * 384;
        int which = rem >> 7;
        int c4    = rem & 127;
        float4 val = gq[(size_t)(n * TT + t) * 384 + rem];
        if (which < 2) { val.x *= scale; val.y *= scale; val.z *= scale; val.w *= scale; }
        float* dst = (which == 0 ? q : which == 1 ? k : v) + t * QP + c4 * 4;
        *(float4*)dst = val;
    }
    const float4* grk = reinterpret_cast<const float4*>(rp_k);
    const float4* grv = reinterpret_cast<const float4*>(rp_v);
    for (int idx = tid; idx < 992; idx += 256) {
        int half = idx >= 496;
        int r = idx - half * 496;
        int row = r >> 4, c4 = r & 15;
        float4 val = (half ? grv : grk)[(49 + row) * 16 + c4];
        *(float4*)((half ? rv : rk) + row * RP + c4 * 4) = val;
    }
    __syncthreads();

    {
        int h = tid >> 5;
        int r5 = tid & 31;
        int tile = r5 & 15;
        int chalf = r5 >> 4;
        int ti = (tile >> 2) << 2;
        int tj = (tile & 3) << 2;
        int cbase = h * 64 + chalf * 32;
        const float* rkb = rk + (ti - tj + 12) * RP + chalf * 32;

        float acc[4][4];
        #pragma unroll
        for (int a = 0; a < 4; a++)
            #pragma unroll
            for (int b = 0; b < 4; b++) acc[a][b] = 0.f;

        #pragma unroll
        for (int c4 = 0; c4 < 8; c4++) {
            int c = cbase + c4 * 4;
            float4 qi[4], kj[4], qj[4], rr[7];
            #pragma unroll
            for (int a = 0; a < 4; a++) qi[a] = *(const float4*)(q + (ti + a) * QP + c);
            #pragma unroll
            for (int b = 0; b < 4; b++) {
                kj[b] = *(const float4*)(k + (tj + b) * QP + c);
                qj[b] = *(const float4*)(q + (tj + b) * QP + c);
            }
            #pragma unroll
            for (int e = 0; e < 7; e++) rr[e] = *(const float4*)(rkb + e * RP + c4 * 4);
            #pragma unroll
            for (int a = 0; a < 4; a++)
                #pragma unroll
                for (int b = 0; b < 4; b++)
                    acc[a][b] += dot4(qi[a], kj[b]) + dot4(qj[b], rr[a - b + 3]);
        }
        #pragma unroll
        for (int a = 0; a < 4; a++)
            #pragma unroll
            for (int b = 0; b < 4; b++) {
                acc[a][b] += __shfl_xor_sync(0xFFFFFFFFu, acc[a][b], 16);
                if (chalf == 0) ws[h * 272 + (ti + a) * 17 + tj + b] = acc[a][b];
            }
    }
    __syncthreads();

    if (tid < 128) {
        int h = tid >> 4, i = tid & 15;
        float* wp = ws + h * 272 + i * 17;
        float mx = -1e30f;
        #pragma unroll
        for (int j = 0; j < 16; j++) mx = fmaxf(mx, wp[j]);
        float e[16]; float sum = 0.f;
        #pragma unroll
        for (int j = 0; j < 16; j++) { e[j] = __expf(wp[j] - mx); sum += e[j]; }
        float inv = 1.f / sum;
        #pragma unroll
        for (int j = 0; j < 16; j++) wp[j] = e[j] * inv;
    }
    __syncthreads();

    {
        int h = tid >> 5;
        int r5 = tid & 31;
        int tgrp = r5 >> 3;
        int cq = r5 & 7;
        int t0 = tgrp * 4;
        int c = h * 64 + cq * 8;
        const float* wsb = ws + h * 272;

        float acc[4][8];
        #pragma unroll
        for (int t = 0; t < 4; t++)
            #pragma unroll
            for (int j = 0; j < 8; j++) acc[t][j] = 0.f;

        #pragma unroll
        for (int s = 0; s < 16; s++) {
            float4 v0 = *(const float4*)(v + s * QP + c);
            float4 v1 = *(const float4*)(v + s * QP + c + 4);
            #pragma unroll
            for (int t = 0; t < 4; t++) {
                float wv = wsb[(t0 + t) * 17 + s];
                acc[t][0] += wv * v0.x; acc[t][1] += wv * v0.y;
                acc[t][2] += wv * v0.z; acc[t][3] += wv * v0.w;
                acc[t][4] += wv * v1.x; acc[t][5] += wv * v1.y;
                acc[t][6] += wv * v1.z; acc[t][7] += wv * v1.w;
            }
        }
        #pragma unroll
        for (int d = 0; d < 31; d++) {
            float4 r0 = *(const float4*)(rv + d * RP + cq * 8);
            float4 r1 = *(const float4*)(rv + d * RP + cq * 8 + 4);
            #pragma unroll
            for (int t = 0; t < 4; t++) {
                int s = d + t0 + t - 15;
                if (s >= 0 && s < 16) {
                    float wv = wsb[(t0 + t) * 17 + s];
                    acc[t][0] += wv * r0.x; acc[t][1] += wv * r0.y;
                    acc[t][2] += wv * r0.z; acc[t][3] += wv * r0.w;
                    acc[t][4] += wv * r1.x; acc[t][5] += wv * r1.y;
                    acc[t][6] += wv * r1.z; acc[t][7] += wv * r1.w;
                }
            }
        }
        #pragma unroll
        for (int t = 0; t < 4; t++) {
            size_t idx = ((size_t)(n * TT + t0 + t)) * CC + c;
            uint4 uh, ul;
            __half hh[8], ll[8];
            #pragma unroll
            for (int j = 0; j < 8; j++) {
                hh[j] = __float2half(acc[t][j]);
                ll[j] = __float2half(acc[t][j] - __half2float(hh[j]));
            }
            uh.x = *(uint32_t*)&hh[0]; uh.y = *(uint32_t*)&hh[2];
            uh.z = *(uint32_t*)&hh[4]; uh.w = *(uint32_t*)&hh[6];
            ul.x = *(uint32_t*)&ll[0]; ul.y = *(uint32_t*)&ll[2];
            ul.z = *(uint32_t*)&ll[4]; ul.w = *(uint32_t*)&ll[6];
            *(uint4*)(g_ah + idx) = uh;
            *(uint4*)(g_al + idx) = ul;
        }
    }
}

// ---------------- 6) transpose back + residual ----------------
__global__ __launch_bounds__(256) void resid_tr(const float* __restrict__ x,
                                                float* __restrict__ out) {
    __shared__ float tile[32][33];
    int bx  = blockIdx.x;
    int hwt = bx & 31;
    int ct  = (bx >> 5) & 15;
    int t   = (bx >> 9) & 15;
    int b   = bx >> 13;
    int tid = threadIdx.x;
    {
        int c_l   = tid & 31;
        int hw_l0 = tid >> 5;
        #pragma unroll
        for (int p = 0; p < 4; p++) {
            int hw_l = hw_l0 + p * 8;
            int hw   = hwt * 32 + hw_l;
            size_t m = ((size_t)(b * HWc + hw)) * TT + t;
            tile[hw_l][c_l] = g_pout[m * CC + ct * 32 + c_l];
        }
    }
    __syncthreads();
    {
        int hw_l = tid & 31;
        int c_l0 = tid >> 5;
        int hw   = hwt * 32 + hw_l;
        #pragma unroll
        for (int p = 0; p < 4; p++) {
            int c_l = c_l0 + p * 8;
            int c   = ct * 32 + c_l;
            size_t idx = (((size_t)b * CC + c) * TT + t) * HWc + hw;
            out[idx] = x[idx] + tile[hw_l][c_l];
        }
    }
}

// ---------------- host launch ----------------
extern "C" void kernel_launch(void* const* d_in, const int* in_sizes, int n_in,
                              void* d_out, int out_size) {
    const float* x      = (const float*)d_in[0];
    const float* gamma  = (const float*)d_in[1];
    const float* beta   = (const float*)d_in[2];
    const float* w_qkv  = (const float*)d_in[3];
    const float* b_qkv  = (const float*)d_in[4];
    const float* rp_k   = (const float*)d_in[5];
    const float* rp_v   = (const float*)d_in[6];
    const float* w_proj = (const float*)d_in[7];
    const float* b_proj = (const float*)d_in[8];
    float* out = (float*)d_out;

    cudaFuncSetAttribute(hmma_gemm, cudaFuncAttributeMaxDynamicSharedMemorySize, GEMM_SMEM);
    cudaFuncSetAttribute(attn, cudaFuncAttributeMaxDynamicSharedMemorySize, ATTN_SMEM);

    __half *wqh, *wql, *wph, *wpl, *nh, *nl, *ah, *al;
    cudaGetSymbolAddress((void**)&wqh, g_wqh);
    cudaGetSymbolAddress((void**)&wql, g_wql);
    cudaGetSymbolAddress((void**)&wph, g_wph);
    cudaGetSymbolAddress((void**)&wpl, g_wpl);
    cudaGetSymbolAddress((void**)&nh, g_nh);
    cudaGetSymbolAddress((void**)&nl, g_nl);
    cudaGetSymbolAddress((void**)&ah, g_ah);
    cudaGetSymbolAddress((void**)&al, g_al);
    float *qkv, *pout;
    cudaGetSymbolAddress((void**)&qkv, g_qkv);
    cudaGetSymbolAddress((void**)&pout, g_pout);

    // hmma_gemm(qkv) stays launch #4 for ncu attribution
    conv_both<<<(C3 * CC / 4 + CC * CC / 4 + 255) / 256, 256>>>(w_qkv, w_proj);
    gn_stats<<<BB * GRP, 1024>>>(x);
    norm_tr<<<BB * TT * (CC / 32) * (HWc / 32), 256>>>(x, gamma, beta);
    hmma_gemm<<<dim3(C3 / 128, MM / 128), 256, GEMM_SMEM>>>(nh, nl, wqh, wql, b_qkv, qkv, C3);
    attn<<<NN, 256, ATTN_SMEM>>>(rp_k, rp_v);
    hmma_gemm<<<dim3(CC / 128, MM / 128), 256, GEMM_SMEM>>>(ah, al, wph, wpl, b_proj, pout, CC);
    resid_tr<<<BB * TT * (CC / 32) * (HWc / 32), 256>>>(x, out);
}

// round 7
// speedup vs baseline: 1.2993x; 1.2993x over previous
#include <cuda_runtime.h>
#include <cuda_fp16.h>
#include <stdint.h>
#include <math.h>

// ---------------- problem constants ----------------
constexpr int BB   = 4;
constexpr int CC   = 512;
constexpr int TT   = 16;
constexpr int HWc  = 1024;
constexpr int NN   = BB * HWc;      // 4096
constexpr int MM   = NN * TT;       // 65536
constexpr int NH   = 8;
constexpr int CH   = 64;
constexpr int GRP  = 32;
constexpr int CPG  = CC / GRP;      // 16
constexpr int C3   = 3 * CC;        // 1536
constexpr float EPSF = 1e-6f;

// ---------------- scratch (static device globals) ----------------
__device__ float g_mean[BB * GRP * HWc];
__device__ float g_rstd[BB * GRP * HWc];
__device__ __half g_nh[(size_t)MM * CC];            // normed activations (hi only)
__device__ __half g_wqh[C3 * CC], g_wql[C3 * CC];   // qkv weights hi/lo
__device__ __half g_wph[CC * CC], g_wpl[CC * CC];   // proj weights hi/lo
__device__ float g_qkv[(size_t)MM * C3];
__device__ __half g_ah[(size_t)MM * CC];            // attention out (hi only)
__device__ float g_pout[(size_t)MM * CC];

// ---------------- helpers ----------------
__device__ __forceinline__ uint32_t smem_u32(const void* p) {
    uint32_t a;
    asm("{ .reg .u64 t; cvta.to.shared.u64 t, %1; cvt.u32.u64 %0, t; }" : "=r"(a) : "l"(p));
    return a;
}
__device__ __forceinline__ void cpasync16(uint32_t dst, const void* src) {
    asm volatile("cp.async.cg.shared.global [%0], [%1], 16;" :: "r"(dst), "l"(src));
}
__device__ __forceinline__ void ldsm4(uint32_t* r, uint32_t a) {
    asm volatile("ldmatrix.sync.aligned.m8n8.x4.shared.b16 {%0,%1,%2,%3}, [%4];"
                 : "=r"(r[0]), "=r"(r[1]), "=r"(r[2]), "=r"(r[3]) : "r"(a));
}
__device__ __forceinline__ void mma16816(float* d, const uint32_t* a, uint32_t b0, uint32_t b1) {
    asm volatile(
        "mma.sync.aligned.m16n8k16.row.col.f32.f16.f16.f32 "
        "{%0,%1,%2,%3},{%4,%5,%6,%7},{%8,%9},{%0,%1,%2,%3};"
        : "+f"(d[0]), "+f"(d[1]), "+f"(d[2]), "+f"(d[3])
        : "r"(a[0]), "r"(a[1]), "r"(a[2]), "r"(a[3]), "r"(b0), "r"(b1));
}
__device__ __forceinline__ float dot4(float4 a, float4 b) {
    return a.x * b.x + a.y * b.y + a.z * b.z + a.w * b.w;
}

// ---------------- 0) split both weight matrices (one launch) ----------------
__global__ __launch_bounds__(256) void conv_both(const float* __restrict__ wq,
                                                 const float* __restrict__ wp) {
    int i4 = blockIdx.x * 256 + threadIdx.x;
    constexpr int NQ4 = C3 * CC / 4;
    constexpr int NP4 = CC * CC / 4;
    const float4* src;
    __half *h, *l;
    int idx;
    if (i4 < NQ4) { src = (const float4*)wq; h = g_wqh; l = g_wql; idx = i4; }
    else if (i4 < NQ4 + NP4) { src = (const float4*)wp; h = g_wph; l = g_wpl; idx = i4 - NQ4; }
    else return;
    float4 v = src[idx];
    float vv[4] = {v.x, v.y, v.z, v.w};
    __half hh[4], ll[4];
    #pragma unroll
    for (int k = 0; k < 4; k++) {
        hh[k] = __float2half(vv[k]);
        ll[k] = __float2half(vv[k] - __half2float(hh[k]));
    }
    uint2 uh, ul;
    uh.x = *(uint32_t*)&hh[0]; uh.y = *(uint32_t*)&hh[2];
    ul.x = *(uint32_t*)&ll[0]; ul.y = *(uint32_t*)&ll[2];
    *(uint2*)(h + idx * 4) = uh;
    *(uint2*)(l + idx * 4) = ul;
}

// ---------------- 1) group-norm statistics ----------------
__global__ __launch_bounds__(1024) void gn_stats(const float* __restrict__ x) {
    int bg = blockIdx.x;
    int b  = bg >> 5;
    int g  = bg & 31;
    int hw = threadIdx.x;
    float sum = 0.f, sq = 0.f;
    const float* base = x + ((size_t)b * CC + (size_t)g * CPG) * TT * HWc + hw;
    #pragma unroll 4
    for (int ct = 0; ct < CPG * TT; ct++) {
        float v = base[(size_t)ct * HWc];
        sum += v; sq += v * v;
    }
    float m   = sum * (1.0f / 256.0f);
    float var = sq  * (1.0f / 256.0f) - m * m;
    g_mean[(size_t)bg * HWc + hw] = m;
    g_rstd[(size_t)bg * HWc + hw] = rsqrtf(var + EPSF);
}

// ---------------- 2) normalize + transpose to fp16 [M,512] ----------------
__global__ __launch_bounds__(256) void norm_tr(const float* __restrict__ x,
                                               const float* __restrict__ gamma,
                                               const float* __restrict__ beta) {
    __shared__ float tile[32][33];
    int bx  = blockIdx.x;
    int hwt = bx & 31;
    int ct  = (bx >> 5) & 15;
    int t   = (bx >> 9) & 15;
    int b   = bx >> 13;
    int tid = threadIdx.x;
    {
        int hw_l = tid & 31;
        int c_l0 = tid >> 5;
        int hw   = hwt * 32 + hw_l;
        #pragma unroll
        for (int p = 0; p < 4; p++) {
            int c_l = c_l0 + p * 8;
            int c   = ct * 32 + c_l;
            int g   = c >> 4;
            float v = x[(((size_t)b * CC + c) * TT + t) * HWc + hw];
            size_t si = ((size_t)(b * GRP + g)) * HWc + hw;
            v = (v - g_mean[si]) * g_rstd[si] * gamma[c] + beta[c];
            tile[c_l][hw_l] = v;
        }
    }
    __syncthreads();
    {
        int c2    = (tid & 15) * 2;
        int hw_l0 = tid >> 4;
        #pragma unroll
        for (int p = 0; p < 2; p++) {
            int hw_l = hw_l0 + p * 16;
            int hw   = hwt * 32 + hw_l;
            size_t m = ((size_t)(b * HWc + hw)) * TT + t;
            float v0 = tile[c2][hw_l];
            float v1 = tile[c2 + 1][hw_l];
            size_t idx = m * CC + ct * 32 + c2;
            *(__half2*)(g_nh + idx) = __halves2half2(__float2half(v0), __float2half(v1));
        }
    }
}

// ---------------- HMMA GEMM: 2-pass split (A*Bh + A*Bl), 2-stage pipeline ----------------
constexpr int PITCH   = 80;
constexpr int TILE_B  = 128 * PITCH;   // 10240
constexpr int STAGE_B = 3 * TILE_B;    // 30720 (A, Bh, Bl)
constexpr int GEMM_SMEM = 2 * STAGE_B; // 61440

__global__ __launch_bounds__(256, 2) void hmma_gemm(const __half* __restrict__ A,
                                                    const __half* __restrict__ Bh,
                                                    const __half* __restrict__ Bl,
                                                    const float* __restrict__ bias,
                                                    float* __restrict__ Cout, int ldc) {
    extern __shared__ char smem[];
    uint32_t sb = smem_u32(smem);
    int tid = threadIdx.x;
    int n0 = blockIdx.x * 128;
    int m0 = blockIdx.y * 128;

    int r = tid >> 2;
    int c = tid & 3;
    const int4* pA  = (const int4*)A  + (size_t)(m0 + r) * 64 + c;
    const int4* pBh = (const int4*)Bh + (size_t)(n0 + r) * 64 + c;
    const int4* pBl = (const int4*)Bl + (size_t)(n0 + r) * 64 + c;
    uint32_t d0 = sb + r * PITCH + c * 16;
    constexpr int RSTEP = 64 * 64;
    constexpr int DSTEP = 64 * PITCH;

    auto issue = [&](int kk, int stage) {
        uint32_t dst = d0 + stage * STAGE_B;
        int ko = kk * 4;
        cpasync16(dst,                       pA  + ko);
        cpasync16(dst + DSTEP,               pA  + ko + RSTEP);
        cpasync16(dst + TILE_B,              pBh + ko);
        cpasync16(dst + TILE_B + DSTEP,      pBh + ko + RSTEP);
        cpasync16(dst + 2 * TILE_B,          pBl + ko);
        cpasync16(dst + 2 * TILE_B + DSTEP,  pBl + ko + RSTEP);
        asm volatile("cp.async.commit_group;");
    };

    float acc[4][4][4];
    #pragma unroll
    for (int a = 0; a < 4; a++)
        #pragma unroll
        for (int b = 0; b < 4; b++)
            #pragma unroll
            for (int cc = 0; cc < 4; cc++) acc[a][b][cc] = 0.f;

    int wid = tid >> 5, lane = tid & 31;
    int mw  = (wid >> 2) * 64;
    int nwv = (wid & 3) * 32;
    int lrow = lane & 15;
    int lk   = (lane >> 4) * 16;
    uint32_t adab = (mw + lrow) * PITCH + lk;
    uint32_t bdab = TILE_B + (nwv + lrow) * PITCH + lk;

    issue(0, 0);

    #pragma unroll 1
    for (int ks = 0; ks < 16; ks++) {
        asm volatile("cp.async.wait_group 0;");
        __syncthreads();
        if (ks + 1 < 16) issue(ks + 1, (ks + 1) & 1);

        uint32_t sa = sb + (ks & 1) * STAGE_B;
        #pragma unroll
        for (int j = 0; j < 2; j++) {
            uint32_t am[4][4], bh[2][4], bl[2][4];
            #pragma unroll
            for (int mt = 0; mt < 4; mt++) {
                uint32_t ad = sa + adab + mt * (16 * PITCH) + j * 32;
                ldsm4(am[mt], ad);
            }
            #pragma unroll
            for (int bt = 0; bt < 2; bt++) {
                uint32_t bd = sa + bdab + bt * (16 * PITCH) + j * 32;
                ldsm4(bh[bt], bd);
                ldsm4(bl[bt], bd + TILE_B);
            }
            #pragma unroll
            for (int mt = 0; mt < 4; mt++)
                #pragma unroll
                for (int nt = 0; nt < 4; nt++) {
                    int bt = nt >> 1, s = nt & 1;
                    mma16816(acc[mt][nt], am[mt], bh[bt][s], bh[bt][2 + s]);
                    mma16816(acc[mt][nt], am[mt], bl[bt][s], bl[bt][2 + s]);
                }
        }
    }

    int row_in = lane >> 2;
    int colq   = (lane & 3) * 2;
    #pragma unroll
    for (int mt = 0; mt < 4; mt++) {
        int gr = m0 + mw + mt * 16 + row_in;
        #pragma unroll
        for (int nt = 0; nt < 4; nt++) {
            int gc = n0 + nwv + nt * 8 + colq;
            float b0 = bias[gc], b1 = bias[gc + 1];
            float2 v0 = make_float2(acc[mt][nt][0] + b0, acc[mt][nt][1] + b1);
            float2 v1 = make_float2(acc[mt][nt][2] + b0, acc[mt][nt][3] + b1);
            *(float2*)(Cout + (size_t)gr * ldc + gc)       = v0;
            *(float2*)(Cout + (size_t)(gr + 8) * ldc + gc) = v1;
        }
    }
}

// ---------------- 4) attention: one block per n, all 8 heads ----------------
constexpr int QP = 516;
constexpr int RP = 68;
constexpr int OFF_Q  = 0;
constexpr int OFF_K  = 16 * QP;
constexpr int OFF_V  = 32 * QP;
constexpr int OFF_RK = 48 * QP;
constexpr int OFF_RV = OFF_RK + 31 * RP;
constexpr int OFF_WS = OFF_RV + 31 * RP;
constexpr int ATTN_SMEM = (OFF_WS + 8 * 16 * 17) * 4;

__global__ __launch_bounds__(256, 1) void attn(const float* __restrict__ rp_k,
                                               const float* __restrict__ rp_v) {
    extern __shared__ float sm[];
    float* q  = sm + OFF_Q;
    float* k  = sm + OFF_K;
    float* v  = sm + OFF_V;
    float* rk = sm + OFF_RK;
    float* rv = sm + OFF_RV;
    float* ws = sm + OFF_WS;

    int n   = blockIdx.x;
    int tid = threadIdx.x;
    const float scale = 0.35355339059327373f;

    const float4* gq = reinterpret_cast<const float4*>(g_qkv);
    #pragma unroll
    for (int it = 0; it < 24; it++) {
        int idx = it * 256 + tid;
        int t   = idx / 384;
        int rem = idx - t * 384;
        int which = rem >> 7;
        int c4    = rem & 127;
        float4 val = gq[(size_t)(n * TT + t) * 384 + rem];
        if (which < 2) { val.x *= scale; val.y *= scale; val.z *= scale; val.w *= scale; }
        float* dst = (which == 0 ? q : which == 1 ? k : v) + t * QP + c4 * 4;
        *(float4*)dst = val;
    }
    const float4* grk = reinterpret_cast<const float4*>(rp_k);
    const float4* grv = reinterpret_cast<const float4*>(rp_v);
    for (int idx = tid; idx < 992; idx += 256) {
        int half = idx >= 496;
        int r = idx - half * 496;
        int row = r >> 4, c4 = r & 15;
        float4 val = (half ? grv : grk)[(49 + row) * 16 + c4];
        *(float4*)((half ? rv : rk) + row * RP + c4 * 4) = val;
    }
    __syncthreads();

    {
        int h = tid >> 5;
        int r5 = tid & 31;
        int tile = r5 & 15;
        int chalf = r5 >> 4;
        int ti = (tile >> 2) << 2;
        int tj = (tile & 3) << 2;
        int cbase = h * 64 + chalf * 32;
        const float* rkb = rk + (ti - tj + 12) * RP + chalf * 32;

        float acc[4][4];
        #pragma unroll
        for (int a = 0; a < 4; a++)
            #pragma unroll
            for (int b = 0; b < 4; b++) acc[a][b] = 0.f;

        #pragma unroll
        for (int c4 = 0; c4 < 8; c4++) {
            int c = cbase + c4 * 4;
            float4 qi[4], kj[4], qj[4], rr[7];
            #pragma unroll
            for (int a = 0; a < 4; a++) qi[a] = *(const float4*)(q + (ti + a) * QP + c);
            #pragma unroll
            for (int b = 0; b < 4; b++) {
                kj[b] = *(const float4*)(k + (tj + b) * QP + c);
                qj[b] = *(const float4*)(q + (tj + b) * QP + c);
            }
            #pragma unroll
            for (int e = 0; e < 7; e++) rr[e] = *(const float4*)(rkb + e * RP + c4 * 4);
            #pragma unroll
            for (int a = 0; a < 4; a++)
                #pragma unroll
                for (int b = 0; b < 4; b++)
                    acc[a][b] += dot4(qi[a], kj[b]) + dot4(qj[b], rr[a - b + 3]);
        }
        #pragma unroll
        for (int a = 0; a < 4; a++)
            #pragma unroll
            for (int b = 0; b < 4; b++) {
                acc[a][b] += __shfl_xor_sync(0xFFFFFFFFu, acc[a][b], 16);
                if (chalf == 0) ws[h * 272 + (ti + a) * 17 + tj + b] = acc[a][b];
            }
    }
    __syncthreads();

    if (tid < 128) {
        int h = tid >> 4, i = tid & 15;
        float* wp = ws + h * 272 + i * 17;
        float mx = -1e30f;
        #pragma unroll
        for (int j = 0; j < 16; j++) mx = fmaxf(mx, wp[j]);
        float e[16]; float sum = 0.f;
        #pragma unroll
        for (int j = 0; j < 16; j++) { e[j] = __expf(wp[j] - mx); sum += e[j]; }
        float inv = 1.f / sum;
        #pragma unroll
        for (int j = 0; j < 16; j++) wp[j] = e[j] * inv;
    }
    __syncthreads();

    {
        int h = tid >> 5;
        int r5 = tid & 31;
        int tgrp = r5 >> 3;
        int cq = r5 & 7;
        int t0 = tgrp * 4;
        int c = h * 64 + cq * 8;
        const float* wsb = ws + h * 272;

        float acc[4][8];
        #pragma unroll
        for (int t = 0; t < 4; t++)
            #pragma unroll
            for (int j = 0; j < 8; j++) acc[t][j] = 0.f;

        #pragma unroll
        for (int s = 0; s < 16; s++) {
            float4 v0 = *(const float4*)(v + s * QP + c);
            float4 v1 = *(const float4*)(v + s * QP + c + 4);
            #pragma unroll
            for (int t = 0; t < 4; t++) {
                float wv = wsb[(t0 + t) * 17 + s];
                acc[t][0] += wv * v0.x; acc[t][1] += wv * v0.y;
                acc[t][2] += wv * v0.z; acc[t][3] += wv * v0.w;
                acc[t][4] += wv * v1.x; acc[t][5] += wv * v1.y;
                acc[t][6] += wv * v1.z; acc[t][7] += wv * v1.w;
            }
        }
        #pragma unroll
        for (int d = 0; d < 31; d++) {
            float4 r0 = *(const float4*)(rv + d * RP + cq * 8);
            float4 r1 = *(const float4*)(rv + d * RP + cq * 8 + 4);
            #pragma unroll
            for (int t = 0; t < 4; t++) {
                int s = d + t0 + t - 15;
                if (s >= 0 && s < 16) {
                    float wv = wsb[(t0 + t) * 17 + s];
                    acc[t][0] += wv * r0.x; acc[t][1] += wv * r0.y;
                    acc[t][2] += wv * r0.z; acc[t][3] += wv * r0.w;
                    acc[t][4] += wv * r1.x; acc[t][5] += wv * r1.y;
                    acc[t][6] += wv * r1.z; acc[t][7] += wv * r1.w;
                }
            }
        }
        #pragma unroll
        for (int t = 0; t < 4; t++) {
            size_t idx = ((size_t)(n * TT + t0 + t)) * CC + c;
            uint4 uh;
            __half hh[8];
            #pragma unroll
            for (int j = 0; j < 8; j++) hh[j] = __float2half(acc[t][j]);
            uh.x = *(uint32_t*)&hh[0]; uh.y = *(uint32_t*)&hh[2];
            uh.z = *(uint32_t*)&hh[4]; uh.w = *(uint32_t*)&hh[6];
            *(uint4*)(g_ah + idx) = uh;
        }
    }
}

// ---------------- 6) transpose back + residual ----------------
__global__ __launch_bounds__(256) void resid_tr(const float* __restrict__ x,
                                                float* __restrict__ out) {
    __shared__ float tile[32][33];
    int bx  = blockIdx.x;
    int hwt = bx & 31;
    int ct  = (bx >> 5) & 15;
    int t   = (bx >> 9) & 15;
    int b   = bx >> 13;
    int tid = threadIdx.x;
    {
        int c_l   = tid & 31;
        int hw_l0 = tid >> 5;
        #pragma unroll
        for (int p = 0; p < 4; p++) {
            int hw_l = hw_l0 + p * 8;
            int hw   = hwt * 32 + hw_l;
            size_t m = ((size_t)(b * HWc + hw)) * TT + t;
            tile[hw_l][c_l] = g_pout[m * CC + ct * 32 + c_l];
        }
    }
    __syncthreads();
    {
        int hw_l = tid & 31;
        int c_l0 = tid >> 5;
        int hw   = hwt * 32 + hw_l;
        #pragma unroll
        for (int p = 0; p < 4; p++) {
            int c_l = c_l0 + p * 8;
            int c   = ct * 32 + c_l;
            size_t idx = (((size_t)b * CC + c) * TT + t) * HWc + hw;
            out[idx] = x[idx] + tile[hw_l][c_l];
        }
    }
}

// ---------------- host launch ----------------
extern "C" void kernel_launch(void* const* d_in, const int* in_sizes, int n_in,
                              void* d_out, int out_size) {
    const float* x      = (const float*)d_in[0];
    const float* gamma  = (const float*)d_in[1];
    const float* beta   = (const float*)d_in[2];
    const float* w_qkv  = (const float*)d_in[3];
    const float* b_qkv  = (const float*)d_in[4];
    const float* rp_k   = (const float*)d_in[5];
    const float* rp_v   = (const float*)d_in[6];
    const float* w_proj = (const float*)d_in[7];
    const float* b_proj = (const float*)d_in[8];
    float* out = (float*)d_out;

    cudaFuncSetAttribute(hmma_gemm, cudaFuncAttributeMaxDynamicSharedMemorySize, GEMM_SMEM);
    cudaFuncSetAttribute(attn, cudaFuncAttributeMaxDynamicSharedMemorySize, ATTN_SMEM);

    __half *wqh, *wql, *wph, *wpl, *nh, *ah;
    cudaGetSymbolAddress((void**)&wqh, g_wqh);
    cudaGetSymbolAddress((void**)&wql, g_wql);
    cudaGetSymbolAddress((void**)&wph, g_wph);
    cudaGetSymbolAddress((void**)&wpl, g_wpl);
    cudaGetSymbolAddress((void**)&nh, g_nh);
    cudaGetSymbolAddress((void**)&ah, g_ah);
    float *qkv, *pout;
    cudaGetSymbolAddress((void**)&qkv, g_qkv);
    cudaGetSymbolAddress((void**)&pout, g_pout);

    // hmma_gemm(qkv) stays launch #4 for ncu attribution
    conv_both<<<(C3 * CC / 4 + CC * CC / 4 + 255) / 256, 256>>>(w_qkv, w_proj);
    gn_stats<<<BB * GRP, 1024>>>(x);
    norm_tr<<<BB * TT * (CC / 32) * (HWc / 32), 256>>>(x, gamma, beta);
    hmma_gemm<<<dim3(C3 / 128, MM / 128), 256, GEMM_SMEM>>>(nh, wqh, wql, b_qkv, qkv, C3);
    attn<<<NN, 256, ATTN_SMEM>>>(rp_k, rp_v);
    hmma_gemm<<<dim3(CC / 128, MM / 128), 256, GEMM_SMEM>>>(ah, wph, wpl, b_proj, pout, CC);
    resid_tr<<<BB * TT * (CC / 32) * (HWc / 32), 256>>>(x, out);
}

// round 8
// speedup vs baseline: 1.7133x; 1.3187x over previous
#include <cuda_runtime.h>
#include <cuda_fp16.h>
#include <stdint.h>
#include <math.h>

// ---------------- problem constants ----------------
constexpr int BB   = 4;
constexpr int CC   = 512;
constexpr int TT   = 16;
constexpr int HWc  = 1024;
constexpr int NN   = BB * HWc;      // 4096
constexpr int MM   = NN * TT;       // 65536
constexpr int NH   = 8;
constexpr int CH   = 64;
constexpr int GRP  = 32;
constexpr int CPG  = CC / GRP;      // 16
constexpr int C3   = 3 * CC;        // 1536
constexpr float EPSF = 1e-6f;

// ---------------- scratch (static device globals) ----------------
__device__ float g_mean[BB * GRP * HWc];
__device__ float g_rstd[BB * GRP * HWc];
__device__ __half g_nh[(size_t)MM * CC];    // normed activations (fp16)
__device__ __half g_wqh[C3 * CC];           // qkv weights (fp16)
__device__ __half g_wph[CC * CC];           // proj weights (fp16)
__device__ float g_qkv[(size_t)MM * C3];
__device__ __half g_ah[(size_t)MM * CC];    // attention out (fp16)
__device__ float g_pout[(size_t)MM * CC];

// ---------------- helpers ----------------
__device__ __forceinline__ uint32_t smem_u32(const void* p) {
    uint32_t a;
    asm("{ .reg .u64 t; cvta.to.shared.u64 t, %1; cvt.u32.u64 %0, t; }" : "=r"(a) : "l"(p));
    return a;
}
__device__ __forceinline__ void cpasync16(uint32_t dst, const void* src) {
    asm volatile("cp.async.cg.shared.global [%0], [%1], 16;" :: "r"(dst), "l"(src));
}
__device__ __forceinline__ void ldsm4(uint32_t* r, uint32_t a) {
    asm volatile("ldmatrix.sync.aligned.m8n8.x4.shared.b16 {%0,%1,%2,%3}, [%4];"
                 : "=r"(r[0]), "=r"(r[1]), "=r"(r[2]), "=r"(r[3]) : "r"(a));
}
__device__ __forceinline__ void mma16816(float* d, const uint32_t* a, uint32_t b0, uint32_t b1) {
    asm volatile(
        "mma.sync.aligned.m16n8k16.row.col.f32.f16.f16.f32 "
        "{%0,%1,%2,%3},{%4,%5,%6,%7},{%8,%9},{%0,%1,%2,%3};"
        : "+f"(d[0]), "+f"(d[1]), "+f"(d[2]), "+f"(d[3])
        : "r"(a[0]), "r"(a[1]), "r"(a[2]), "r"(a[3]), "r"(b0), "r"(b1));
}
__device__ __forceinline__ float dot4(float4 a, float4 b) {
    return a.x * b.x + a.y * b.y + a.z * b.z + a.w * b.w;
}

// ---------------- 0) convert both weight matrices to fp16 ----------------
__global__ __launch_bounds__(256) void conv_both(const float* __restrict__ wq,
                                                 const float* __restrict__ wp) {
    int i4 = blockIdx.x * 256 + threadIdx.x;
    constexpr int NQ4 = C3 * CC / 4;
    constexpr int NP4 = CC * CC / 4;
    const float4* src;
    __half* h;
    int idx;
    if (i4 < NQ4) { src = (const float4*)wq; h = g_wqh; idx = i4; }
    else if (i4 < NQ4 + NP4) { src = (const float4*)wp; h = g_wph; idx = i4 - NQ4; }
    else return;
    float4 v = src[idx];
    __half hh[4] = {__float2half(v.x), __float2half(v.y), __float2half(v.z), __float2half(v.w)};
    uint2 uh;
    uh.x = *(uint32_t*)&hh[0]; uh.y = *(uint32_t*)&hh[2];
    *(uint2*)(h + idx * 4) = uh;
}

// ---------------- 1) group-norm statistics ----------------
__global__ __launch_bounds__(1024) void gn_stats(const float* __restrict__ x) {
    int bg = blockIdx.x;
    int b  = bg >> 5;
    int g  = bg & 31;
    int hw = threadIdx.x;
    float sum = 0.f, sq = 0.f;
    const float* base = x + ((size_t)b * CC + (size_t)g * CPG) * TT * HWc + hw;
    #pragma unroll 4
    for (int ct = 0; ct < CPG * TT; ct++) {
        float v = base[(size_t)ct * HWc];
        sum += v; sq += v * v;
    }
    float m   = sum * (1.0f / 256.0f);
    float var = sq  * (1.0f / 256.0f) - m * m;
    g_mean[(size_t)bg * HWc + hw] = m;
    g_rstd[(size_t)bg * HWc + hw] = rsqrtf(var + EPSF);
}

// ---------------- 2) normalize + transpose to fp16 [M,512] ----------------
__global__ __launch_bounds__(256) void norm_tr(const float* __restrict__ x,
                                               const float* __restrict__ gamma,
                                               const float* __restrict__ beta) {
    __shared__ float tile[32][33];
    int bx  = blockIdx.x;
    int hwt = bx & 31;
    int ct  = (bx >> 5) & 15;
    int t   = (bx >> 9) & 15;
    int b   = bx >> 13;
    int tid = threadIdx.x;
    {
        int hw_l = tid & 31;
        int c_l0 = tid >> 5;
        int hw   = hwt * 32 + hw_l;
        #pragma unroll
        for (int p = 0; p < 4; p++) {
            int c_l = c_l0 + p * 8;
            int c   = ct * 32 + c_l;
            int g   = c >> 4;
            float v = x[(((size_t)b * CC + c) * TT + t) * HWc + hw];
            size_t si = ((size_t)(b * GRP + g)) * HWc + hw;
            v = (v - g_mean[si]) * g_rstd[si] * gamma[c] + beta[c];
            tile[c_l][hw_l] = v;
        }
    }
    __syncthreads();
    {
        int c2    = (tid & 15) * 2;
        int hw_l0 = tid >> 4;
        #pragma unroll
        for (int p = 0; p < 2; p++) {
            int hw_l = hw_l0 + p * 16;
            int hw   = hwt * 32 + hw_l;
            size_t m = ((size_t)(b * HWc + hw)) * TT + t;
            float v0 = tile[c2][hw_l];
            float v1 = tile[c2 + 1][hw_l];
            size_t idx = m * CC + ct * 32 + c2;
            *(__half2*)(g_nh + idx) = __halves2half2(__float2half(v0), __float2half(v1));
        }
    }
}

// ---------------- HMMA GEMM: single-pass fp16, 2-stage pipeline ----------------
constexpr int PITCH   = 80;
constexpr int TILE_B  = 128 * PITCH;   // 10240
constexpr int STAGE_B = 2 * TILE_B;    // 20480 (A, B)
constexpr int GEMM_SMEM = 2 * STAGE_B; // 40960

__global__ __launch_bounds__(256, 2) void hmma_gemm(const __half* __restrict__ A,
                                                    const __half* __restrict__ B,
                                                    const float* __restrict__ bias,
                                                    float* __restrict__ Cout, int ldc) {
    extern __shared__ char smem[];
    uint32_t sb = smem_u32(smem);
    int tid = threadIdx.x;
    int n0 = blockIdx.x * 128;
    int m0 = blockIdx.y * 128;

    int r = tid >> 2;
    int c = tid & 3;
    const int4* pA = (const int4*)A + (size_t)(m0 + r) * 64 + c;
    const int4* pB = (const int4*)B + (size_t)(n0 + r) * 64 + c;
    uint32_t d0 = sb + r * PITCH + c * 16;
    constexpr int RSTEP = 64 * 64;
    constexpr int DSTEP = 64 * PITCH;

    auto issue = [&](int kk, int stage) {
        uint32_t dst = d0 + stage * STAGE_B;
        int ko = kk * 4;
        cpasync16(dst,                   pA + ko);
        cpasync16(dst + DSTEP,           pA + ko + RSTEP);
        cpasync16(dst + TILE_B,          pB + ko);
        cpasync16(dst + TILE_B + DSTEP,  pB + ko + RSTEP);
        asm volatile("cp.async.commit_group;");
    };

    float acc[4][4][4];
    #pragma unroll
    for (int a = 0; a < 4; a++)
        #pragma unroll
        for (int b = 0; b < 4; b++)
            #pragma unroll
            for (int cc = 0; cc < 4; cc++) acc[a][b][cc] = 0.f;

    int wid = tid >> 5, lane = tid & 31;
    int mw  = (wid >> 2) * 64;
    int nwv = (wid & 3) * 32;
    int lrow = lane & 15;
    int lk   = (lane >> 4) * 16;
    uint32_t adab = (mw + lrow) * PITCH + lk;
    uint32_t bdab = TILE_B + (nwv + lrow) * PITCH + lk;

    issue(0, 0);

    #pragma unroll 1
    for (int ks = 0; ks < 16; ks++) {
        asm volatile("cp.async.wait_group 0;");
        __syncthreads();
        if (ks + 1 < 16) issue(ks + 1, (ks + 1) & 1);

        uint32_t sa = sb + (ks & 1) * STAGE_B;
        #pragma unroll
        for (int j = 0; j < 2; j++) {
            uint32_t am[4][4], bm[2][4];
            #pragma unroll
            for (int mt = 0; mt < 4; mt++)
                ldsm4(am[mt], sa + adab + mt * (16 * PITCH) + j * 32);
            #pragma unroll
            for (int bt = 0; bt < 2; bt++)
                ldsm4(bm[bt], sa + bdab + bt * (16 * PITCH) + j * 32);
            #pragma unroll
            for (int mt = 0; mt < 4; mt++)
                #pragma unroll
                for (int nt = 0; nt < 4; nt++) {
                    int bt = nt >> 1, s = nt & 1;
                    mma16816(acc[mt][nt], am[mt], bm[bt][s], bm[bt][2 + s]);
                }
        }
    }

    int row_in = lane >> 2;
    int colq   = (lane & 3) * 2;
    #pragma unroll
    for (int mt = 0; mt < 4; mt++) {
        int gr = m0 + mw + mt * 16 + row_in;
        #pragma unroll
        for (int nt = 0; nt < 4; nt++) {
            int gc = n0 + nwv + nt * 8 + colq;
            float b0 = bias[gc], b1 = bias[gc + 1];
            float2 v0 = make_float2(acc[mt][nt][0] + b0, acc[mt][nt][1] + b1);
            float2 v1 = make_float2(acc[mt][nt][2] + b0, acc[mt][nt][3] + b1);
            *(float2*)(Cout + (size_t)gr * ldc + gc)       = v0;
            *(float2*)(Cout + (size_t)(gr + 8) * ldc + gc) = v1;
        }
    }
}

// ---------------- 4) attention: one block per n, all 8 heads ----------------
constexpr int QP = 516;
constexpr int RP = 68;
constexpr int OFF_Q  = 0;
constexpr int OFF_K  = 16 * QP;
constexpr int OFF_V  = 32 * QP;
constexpr int OFF_RK = 48 * QP;
constexpr int OFF_RV = OFF_RK + 31 * RP;
constexpr int OFF_WS = OFF_RV + 31 * RP;
constexpr int ATTN_SMEM = (OFF_WS + 8 * 16 * 17) * 4;

__global__ __launch_bounds__(256, 1) void attn(const float* __restrict__ rp_k,
                                               const float* __restrict__ rp_v) {
    extern __shared__ float sm[];
    float* q  = sm + OFF_Q;
    float* k  = sm + OFF_K;
    float* v  = sm + OFF_V;
    float* rk = sm + OFF_RK;
    float* rv = sm + OFF_RV;
    float* ws = sm + OFF_WS;

    int n   = blockIdx.x;
    int tid = threadIdx.x;
    const float scale = 0.35355339059327373f;

    const float4* gq = reinterpret_cast<const float4*>(g_qkv);
    #pragma unroll
    for (int it = 0; it < 24; it++) {
        int idx = it * 256 + tid;
        int t   = idx / 384;
        int rem = idx - t * 384;
        int which = rem >> 7;
        int c4    = rem & 127;
        float4 val = gq[(size_t)(n * TT + t) * 384 + rem];
        if (which < 2) { val.x *= scale; val.y *= scale; val.z *= scale; val.w *= scale; }
        float* dst = (which == 0 ? q : which == 1 ? k : v) + t * QP + c4 * 4;
        *(float4*)dst = val;
    }
    const float4* grk = reinterpret_cast<const float4*>(rp_k);
    const float4* grv = reinterpret_cast<const float4*>(rp_v);
    for (int idx = tid; idx < 992; idx += 256) {
        int half = idx >= 496;
        int r = idx - half * 496;
        int row = r >> 4, c4 = r & 15;
        float4 val = (half ? grv : grk)[(49 + row) * 16 + c4];
        *(float4*)((half ? rv : rk) + row * RP + c4 * 4) = val;
    }
    __syncthreads();

    {
        int h = tid >> 5;
        int r5 = tid & 31;
        int tile = r5 & 15;
        int chalf = r5 >> 4;
        int ti = (tile >> 2) << 2;
        int tj = (tile & 3) << 2;
        int cbase = h * 64 + chalf * 32;
        const float* rkb = rk + (ti - tj + 12) * RP + chalf * 32;

        float acc[4][4];
        #pragma unroll
        for (int a = 0; a < 4; a++)
            #pragma unroll
            for (int b = 0; b < 4; b++) acc[a][b] = 0.f;

        #pragma unroll
        for (int c4 = 0; c4 < 8; c4++) {
            int c = cbase + c4 * 4;
            float4 qi[4], kj[4], qj[4], rr[7];
            #pragma unroll
            for (int a = 0; a < 4; a++) qi[a] = *(const float4*)(q + (ti + a) * QP + c);
            #pragma unroll
            for (int b = 0; b < 4; b++) {
                kj[b] = *(const float4*)(k + (tj + b) * QP + c);
                qj[b] = *(const float4*)(q + (tj + b) * QP + c);
            }
            #pragma unroll
            for (int e = 0; e < 7; e++) rr[e] = *(const float4*)(rkb + e * RP + c4 * 4);
            #pragma unroll
            for (int a = 0; a < 4; a++)
                #pragma unroll
                for (int b = 0; b < 4; b++)
                    acc[a][b] += dot4(qi[a], kj[b]) + dot4(qj[b], rr[a - b + 3]);
        }
        #pragma unroll
        for (int a = 0; a < 4; a++)
            #pragma unroll
            for (int b = 0; b < 4; b++) {
                acc[a][b] += __shfl_xor_sync(0xFFFFFFFFu, acc[a][b], 16);
                if (chalf == 0) ws[h * 272 + (ti + a) * 17 + tj + b] = acc[a][b];
            }
    }
    __syncthreads();

    if (tid < 128) {
        int h = tid >> 4, i = tid & 15;
        float* wp = ws + h * 272 + i * 17;
        float mx = -1e30f;
        #pragma unroll
        for (int j = 0; j < 16; j++) mx = fmaxf(mx, wp[j]);
        float e[16]; float sum = 0.f;
        #pragma unroll
        for (int j = 0; j < 16; j++) { e[j] = __expf(wp[j] - mx); sum += e[j]; }
        float inv = 1.f / sum;
        #pragma unroll
        for (int j = 0; j < 16; j++) wp[j] = e[j] * inv;
    }
    __syncthreads();

    {
        int h = tid >> 5;
        int r5 = tid & 31;
        int tgrp = r5 >> 3;
        int cq = r5 & 7;
        int t0 = tgrp * 4;
        int c = h * 64 + cq * 8;
        const float* wsb = ws + h * 272;

        float acc[4][8];
        #pragma unroll
        for (int t = 0; t < 4; t++)
            #pragma unroll
            for (int j = 0; j < 8; j++) acc[t][j] = 0.f;

        #pragma unroll
        for (int s = 0; s < 16; s++) {
            float4 v0 = *(const float4*)(v + s * QP + c);
            float4 v1 = *(const float4*)(v + s * QP + c + 4);
            #pragma unroll
            for (int t = 0; t < 4; t++) {
                float wv = wsb[(t0 + t) * 17 + s];
                acc[t][0] += wv * v0.x; acc[t][1] += wv * v0.y;
                acc[t][2] += wv * v0.z; acc[t][3] += wv * v0.w;
                acc[t][4] += wv * v1.x; acc[t][5] += wv * v1.y;
                acc[t][6] += wv * v1.z; acc[t][7] += wv * v1.w;
            }
        }
        #pragma unroll
        for (int d = 0; d < 31; d++) {
            float4 r0 = *(const float4*)(rv + d * RP + cq * 8);
            float4 r1 = *(const float4*)(rv + d * RP + cq * 8 + 4);
            #pragma unroll
            for (int t = 0; t < 4; t++) {
                int s = d + t0 + t - 15;
                if (s >= 0 && s < 16) {
                    float wv = wsb[(t0 + t) * 17 + s];
                    acc[t][0] += wv * r0.x; acc[t][1] += wv * r0.y;
                    acc[t][2] += wv * r0.z; acc[t][3] += wv * r0.w;
                    acc[t][4] += wv * r1.x; acc[t][5] += wv * r1.y;
                    acc[t][6] += wv * r1.z; acc[t][7] += wv * r1.w;
                }
            }
        }
        #pragma unroll
        for (int t = 0; t < 4; t++) {
            size_t idx = ((size_t)(n * TT + t0 + t)) * CC + c;
            uint4 uh;
            __half hh[8];
            #pragma unroll
            for (int j = 0; j < 8; j++) hh[j] = __float2half(acc[t][j]);
            uh.x = *(uint32_t*)&hh[0]; uh.y = *(uint32_t*)&hh[2];
            uh.z = *(uint32_t*)&hh[4]; uh.w = *(uint32_t*)&hh[6];
            *(uint4*)(g_ah + idx) = uh;
        }
    }
}

// ---------------- 6) transpose back + residual ----------------
__global__ __launch_bounds__(256) void resid_tr(const float* __restrict__ x,
                                                float* __restrict__ out) {
    __shared__ float tile[32][33];
    int bx  = blockIdx.x;
    int hwt = bx & 31;
    int ct  = (bx >> 5) & 15;
    int t   = (bx >> 9) & 15;
    int b   = bx >> 13;
    int tid = threadIdx.x;
    {
        int c_l   = tid & 31;
        int hw_l0 = tid >> 5;
        #pragma unroll
        for (int p = 0; p < 4; p++) {
            int hw_l = hw_l0 + p * 8;
            int hw   = hwt * 32 + hw_l;
            size_t m = ((size_t)(b * HWc + hw)) * TT + t;
            tile[hw_l][c_l] = g_pout[m * CC + ct * 32 + c_l];
        }
    }
    __syncthreads();
    {
        int hw_l = tid & 31;
        int c_l0 = tid >> 5;
        int hw   = hwt * 32 + hw_l;
        #pragma unroll
        for (int p = 0; p < 4; p++) {
            int c_l = c_l0 + p * 8;
            int c   = ct * 32 + c_l;
            size_t idx = (((size_t)b * CC + c) * TT + t) * HWc + hw;
            out[idx] = x[idx] + tile[hw_l][c_l];
        }
    }
}

// ---------------- host launch ----------------
extern "C" void kernel_launch(void* const* d_in, const int* in_sizes, int n_in,
                              void* d_out, int out_size) {
    const float* x      = (const float*)d_in[0];
    const float* gamma  = (const float*)d_in[1];
    const float* beta   = (const float*)d_in[2];
    const float* w_qkv  = (const float*)d_in[3];
    const float* b_qkv  = (const float*)d_in[4];
    const float* rp_k   = (const float*)d_in[5];
    const float* rp_v   = (const float*)d_in[6];
    const float* w_proj = (const float*)d_in[7];
    const float* b_proj = (const float*)d_in[8];
    float* out = (float*)d_out;

    cudaFuncSetAttribute(hmma_gemm, cudaFuncAttributeMaxDynamicSharedMemorySize, GEMM_SMEM);
    cudaFuncSetAttribute(attn, cudaFuncAttributeMaxDynamicSharedMemorySize, ATTN_SMEM);

    __half *wqh, *wph, *nh, *ah;
    cudaGetSymbolAddress((void**)&wqh, g_wqh);
    cudaGetSymbolAddress((void**)&wph, g_wph);
    cudaGetSymbolAddress((void**)&nh, g_nh);
    cudaGetSymbolAddress((void**)&ah, g_ah);
    float *qkv, *pout;
    cudaGetSymbolAddress((void**)&qkv, g_qkv);
    cudaGetSymbolAddress((void**)&pout, g_pout);

    // hmma_gemm(qkv) stays launch #4 for ncu attribution
    conv_both<<<(C3 * CC / 4 + CC * CC / 4 + 255) / 256, 256>>>(w_qkv, w_proj);
    gn_stats<<<BB * GRP, 1024>>>(x);
    norm_tr<<<BB * TT * (CC / 32) * (HWc / 32), 256>>>(x, gamma, beta);
    hmma_gemm<<<dim3(C3 / 128, MM / 128), 256, GEMM_SMEM>>>(nh, wqh, b_qkv, qkv, C3);
    attn<<<NN, 256, ATTN_SMEM>>>(rp_k, rp_v);
    hmma_gemm<<<dim3(CC / 128, MM / 128), 256, GEMM_SMEM>>>(ah, wph, b_proj, pout, CC);
    resid_tr<<<BB * TT * (CC / 32) * (HWc / 32), 256>>>(x, out);
}